// round 3
// baseline (speedup 1.0000x reference)
#include <cuda_runtime.h>
#include <cstdint>

#define CC 256
#define BB 1024
typedef unsigned long long ull;

// Expanded symmetric edge-weight matrix: W[j*CC + c] = w3[e(min(c,j),max(c,j))], diag 0.
__device__ float g_W[CC * CC];

__global__ void build_W_kernel(const float* __restrict__ w3) {
    int idx = blockIdx.x * blockDim.x + threadIdx.x;
    if (idx >= CC * CC) return;
    int c = idx >> 8;
    int j = idx & 255;
    float v = 0.0f;
    if (c != j) {
        int p = c < j ? c : j;
        int q = c < j ? j : c;
        // np.triu_indices(CC, k=1) linearization
        int e = p * (2 * CC - p - 1) / 2 + (q - p - 1);
        v = w3[e];
    }
    g_W[idx] = v;
}

// ---- packed f32x2 helpers (sm_100a) ----
__device__ __forceinline__ ull pk2(float lo, float hi) {
    ull r;
    asm("mov.b64 %0, {%1, %2};" : "=l"(r) : "f"(lo), "f"(hi));
    return r;
}
__device__ __forceinline__ void upk2(ull v, float& lo, float& hi) {
    asm("mov.b64 {%0, %1}, %2;" : "=f"(lo), "=f"(hi) : "l"(v));
}
__device__ __forceinline__ ull add2(ull a, ull b) {
    ull r;
    asm("add.rn.f32x2 %0, %1, %2;" : "=l"(r) : "l"(a), "l"(b));
    return r;
}
__device__ __forceinline__ ull mul2(ull a, ull b) {
    ull r;
    asm("mul.rn.f32x2 %0, %1, %2;" : "=l"(r) : "l"(a), "l"(b));
    return r;
}
__device__ __forceinline__ ull fma2_(ull a, ull b, ull c) {
    ull r;
    asm("fma.rn.f32x2 %0, %1, %2, %3;" : "=l"(r) : "l"(a), "l"(b), "l"(c));
    return r;
}

// out[b,c] = sum_j u(|d|) * (x_j - x_c) * W[j,c],  d = x_c - x_j (sign folded into d')
// u(a) = 0.505*t + 0.495*|t|,  t = w2[0] + a*(w2[1] + a*(w2[2] + a*w2[3]))
//
// Layout: grid = 512 blocks (one row-pair each), blockDim = (256 channels, 2 j-halves).
// Each thread sums 128 j's; halves combined through shared memory.
__global__ __launch_bounds__(512, 4) void son_main_kernel(
    const float* __restrict__ x, const float* __restrict__ w1,
    const float* __restrict__ w2, float* __restrict__ out)
{
    __shared__ float2 xs[CC];        // xs[j] = (row r0, row r0+1) scaled by w1[j]
    __shared__ ull partial[CC];      // j-half 1 partial sums

    const int c = threadIdx.x;       // channel
    const int h = threadIdx.y;       // j-half (0 or 1)
    const int r0 = blockIdx.x * 2;

    if (h == 0) {
        float w1j = w1[c];
        float a0 = x[r0 * CC + c] * w1j;
        float a1 = x[(r0 + 1) * CC + c] * w1j;
        xs[c] = make_float2(a0, a1);
    }
    __syncthreads();

    const float c0 = w2[0], c1 = w2[1], c2 = w2[2], c3 = w2[3];
    const ull C0 = pk2(c0, c0), C1 = pk2(c1, c1);
    const ull C2 = pk2(c2, c2), C3 = pk2(c3, c3);
    const ull P5 = pk2(0.505f, 0.505f), P4 = pk2(0.495f, 0.495f);
    const ull AMASK = 0x7fffffff7fffffffULL;
    const ull SMASK = 0x8000000080000000ULL;

    const ull xc  = *reinterpret_cast<const ull*>(&xs[c]);
    const ull nxc = xc ^ SMASK;      // (-x_c row0, -x_c row1) via sign-bit flip (alu pipe)

    const float*  wp  = g_W + h * 128 * CC + c;
    const float2* xjp = xs + h * 128;

    ull acc = 0ULL;                   // (0.0f, 0.0f)
#pragma unroll 8
    for (int j = 0; j < 128; j++) {
        float w = __ldg(wp + j * CC);                 // coalesced, L2-resident
        ull w2p = pk2(w, w);
        ull xj  = *reinterpret_cast<const ull*>(xjp + j);   // LDS.64 broadcast
        ull d   = add2(xj, nxc);                      // d' = x_j - x_c (both rows)
        ull a   = d & AMASK;                          // |d|
        ull t   = fma2_(C3, a, C2);
        t = fma2_(t, a, C1);
        t = fma2_(t, a, C0);
        ull u   = fma2_(P4, t & AMASK, mul2(P5, t));  // 0.505 t + 0.495 |t|
        acc = fma2_(u, mul2(d, w2p), acc);            // += u * d' * w
    }

    if (h == 1) partial[c] = acc;
    __syncthreads();
    if (h == 0) {
        acc = add2(acc, partial[c]);
        float lo, hi;
        upk2(acc, lo, hi);
        out[r0 * CC + c]       = lo;
        out[(r0 + 1) * CC + c] = hi;
    }
}

extern "C" void kernel_launch(void* const* d_in, const int* in_sizes, int n_in,
                              void* d_out, int out_size) {
    // Identify inputs by element count (robust to ordering):
    // x: 262144, w1: 256, w2: 4, w3: 32640, diff_indices: 8355840 (unused)
    const float* x = nullptr;
    const float* w1 = nullptr;
    const float* w2 = nullptr;
    const float* w3 = nullptr;
    for (int i = 0; i < n_in; i++) {
        switch (in_sizes[i]) {
            case BB * CC:            x  = (const float*)d_in[i]; break;
            case CC:                 w1 = (const float*)d_in[i]; break;
            case 4:                  w2 = (const float*)d_in[i]; break;
            case CC * (CC - 1) / 2:  w3 = (const float*)d_in[i]; break;
            default: break;  // diff_indices not needed
        }
    }

    build_W_kernel<<<(CC * CC + 255) / 256, 256>>>(w3);
    son_main_kernel<<<BB / 2, dim3(CC, 2)>>>(x, w1, w2, (float*)d_out);
}

// round 4
// speedup vs baseline: 1.0981x; 1.0981x over previous
#include <cuda_runtime.h>
#include <cstdint>

#define CC 256
#define BB 1024
typedef unsigned long long ull;

// Pre-expanded duplicated edge weights:
// g_W4[jj*CC + c] = float4( w(2jj,c), w(2jj,c), w(2jj+1,c), w(2jj+1,c) )
// where w(j,c) = w3[e(min(j,c),max(j,c))], w(j,j)=0. 512 KB, L2-resident.
__device__ float4 g_W4[(CC / 2) * CC];

__device__ __forceinline__ float edge_w(const float* __restrict__ w3, int j, int c) {
    if (j == c) return 0.0f;
    int p = j < c ? j : c;
    int q = j < c ? c : j;
    int e = p * (2 * CC - p - 1) / 2 + (q - p - 1);   // np.triu_indices(CC,1) linearization
    return w3[e];
}

__global__ void build_W4_kernel(const float* __restrict__ w3) {
    int idx = blockIdx.x * blockDim.x + threadIdx.x;   // over (CC/2)*CC entries
    if (idx >= (CC / 2) * CC) return;
    int jj = idx >> 8;
    int c  = idx & 255;
    float w0 = edge_w(w3, 2 * jj, c);
    float w1 = edge_w(w3, 2 * jj + 1, c);
    g_W4[idx] = make_float4(w0, w0, w1, w1);
}

// ---- packed f32x2 helpers (sm_100a) ----
__device__ __forceinline__ ull pk2(float lo, float hi) {
    ull r;
    asm("mov.b64 %0, {%1, %2};" : "=l"(r) : "f"(lo), "f"(hi));
    return r;
}
__device__ __forceinline__ void upk2(ull v, float& lo, float& hi) {
    asm("mov.b64 {%0, %1}, %2;" : "=f"(lo), "=f"(hi) : "l"(v));
}
__device__ __forceinline__ ull add2(ull a, ull b) {
    ull r;
    asm("add.rn.f32x2 %0, %1, %2;" : "=l"(r) : "l"(a), "l"(b));
    return r;
}
__device__ __forceinline__ ull mul2(ull a, ull b) {
    ull r;
    asm("mul.rn.f32x2 %0, %1, %2;" : "=l"(r) : "l"(a), "l"(b));
    return r;
}
__device__ __forceinline__ ull fma2_(ull a, ull b, ull c) {
    ull r;
    asm("fma.rn.f32x2 %0, %1, %2, %3;" : "=l"(r) : "l"(a), "l"(b), "l"(c));
    return r;
}

// out[b,c] = sum_j u * (x_j - x_c) * W[j,c]
// t' = 0.505*(w2[0] + a w2[1] + a^2 w2[2] + a^3 w2[3]),  a = |x_c - x_j|
// u  = t' + (0.495/0.505)*|t'|        (== 0.505 t + 0.495 |t|, the leaky-relu slope)
//
// grid = 512 blocks (one packed row-pair each), blockDim = (256 channels, 2 j-halves).
// Each thread handles 128 j's as 64 jj double-steps; halves combined via smem.
__global__ __launch_bounds__(512, 3) void son_main_kernel(
    const float* __restrict__ x, const float* __restrict__ w1,
    const float* __restrict__ w2, float* __restrict__ out)
{
    __shared__ float4 xs4[CC / 2];   // ((float2*)xs4)[j] = (row r0, row r0+1) * w1[j]
    __shared__ ull partial[CC];

    const int c = threadIdx.x;
    const int h = threadIdx.y;
    const int r0 = blockIdx.x * 2;

    if (h == 0) {
        float w1j = w1[c];
        float a0 = x[r0 * CC + c] * w1j;
        float a1 = x[(r0 + 1) * CC + c] * w1j;
        reinterpret_cast<float2*>(xs4)[c] = make_float2(a0, a1);
    }
    __syncthreads();

    // prescaled polynomial coefficients (x 0.505)
    const float s0 = 0.505f * w2[0], s1 = 0.505f * w2[1];
    const float s2 = 0.505f * w2[2], s3 = 0.505f * w2[3];
    const ull C0 = pk2(s0, s0), C1 = pk2(s1, s1);
    const ull C2 = pk2(s2, s2), C3 = pk2(s3, s3);
    const float kf = 0.495f / 0.505f;
    const ull K = pk2(kf, kf);
    const ull AMASK = 0x7fffffff7fffffffULL;
    const ull SMASK = 0x8000000080000000ULL;

    const ull xc  = reinterpret_cast<const ull*>(xs4)[c];
    const ull nxc = xc ^ SMASK;                   // (-x_c, -x_c) via sign flip (alu pipe)

    const float4* wp = g_W4 + h * 64 * CC + c;    // stride CC float4 per jj
    const float4* xp = xs4 + h * 64;

    ull acc0 = 0ULL, acc1 = 0ULL;
#pragma unroll 2
    for (int jj = 0; jj < 64; jj++) {
        float4 wq = __ldg(wp + jj * CC);          // (w_j0, w_j0, w_j1, w_j1), LDG.128
        float4 xq = xp[jj];                       // (xj0.lo, xj0.hi, xj1.lo, xj1.hi), LDS.128
        ull w0 = pk2(wq.x, wq.y), w1p = pk2(wq.z, wq.w);
        ull xj0 = pk2(xq.x, xq.y), xj1 = pk2(xq.z, xq.w);
        // j0
        ull d0 = add2(xj0, nxc);
        ull a0 = d0 & AMASK;
        ull t0 = fma2_(C3, a0, C2);
        t0 = fma2_(t0, a0, C1);
        t0 = fma2_(t0, a0, C0);
        ull u0 = fma2_(K, t0 & AMASK, t0);
        acc0 = fma2_(u0, mul2(d0, w0), acc0);
        // j1
        ull d1 = add2(xj1, nxc);
        ull a1 = d1 & AMASK;
        ull t1 = fma2_(C3, a1, C2);
        t1 = fma2_(t1, a1, C1);
        t1 = fma2_(t1, a1, C0);
        ull u1 = fma2_(K, t1 & AMASK, t1);
        acc1 = fma2_(u1, mul2(d1, w1p), acc1);
    }
    ull acc = add2(acc0, acc1);

    if (h == 1) partial[c] = acc;
    __syncthreads();
    if (h == 0) {
        acc = add2(acc, partial[c]);
        float lo, hi;
        upk2(acc, lo, hi);
        out[r0 * CC + c]       = lo;
        out[(r0 + 1) * CC + c] = hi;
    }
}

extern "C" void kernel_launch(void* const* d_in, const int* in_sizes, int n_in,
                              void* d_out, int out_size) {
    // Identify inputs by element count (robust to ordering):
    // x: 262144, w1: 256, w2: 4, w3: 32640, diff_indices: 8355840 (unused)
    const float* x = nullptr;
    const float* w1 = nullptr;
    const float* w2 = nullptr;
    const float* w3 = nullptr;
    for (int i = 0; i < n_in; i++) {
        switch (in_sizes[i]) {
            case BB * CC:            x  = (const float*)d_in[i]; break;
            case CC:                 w1 = (const float*)d_in[i]; break;
            case 4:                  w2 = (const float*)d_in[i]; break;
            case CC * (CC - 1) / 2:  w3 = (const float*)d_in[i]; break;
            default: break;  // diff_indices not needed
        }
    }

    build_W4_kernel<<<((CC / 2) * CC + 255) / 256, 256>>>(w3);
    son_main_kernel<<<BB / 2, dim3(CC, 2)>>>(x, w1, w2, (float*)d_out);
}

// round 5
// speedup vs baseline: 1.3278x; 1.2092x over previous
#include <cuda_runtime.h>
#include <cstdint>

#define CC 256
#define BB 1024
typedef unsigned long long ull;

// Duplicated edge weights: g_W2[j*CC + c] = float2(w, w), w = w3[e(min(j,c),max(j,c))], diag 0.
// 512 KB, L2-resident. LDG.64 gives an aligned register pair -> no packing MOVs.
__device__ float2 g_W2[CC * CC];

__global__ void build_W2_kernel(const float* __restrict__ w3) {
    int idx = blockIdx.x * blockDim.x + threadIdx.x;
    if (idx >= CC * CC) return;
    int j = idx >> 8;
    int c = idx & 255;
    float v = 0.0f;
    if (j != c) {
        int p = j < c ? j : c;
        int q = j < c ? c : j;
        int e = p * (2 * CC - p - 1) / 2 + (q - p - 1);  // np.triu_indices(CC,1)
        v = w3[e];
    }
    g_W2[idx] = make_float2(v, v);
}

// ---- packed f32x2 helpers (sm_100a) ----
__device__ __forceinline__ ull pk2(float lo, float hi) {
    ull r;
    asm("mov.b64 %0, {%1, %2};" : "=l"(r) : "f"(lo), "f"(hi));
    return r;
}
__device__ __forceinline__ void upk2(ull v, float& lo, float& hi) {
    asm("mov.b64 {%0, %1}, %2;" : "=f"(lo), "=f"(hi) : "l"(v));
}
__device__ __forceinline__ ull add2(ull a, ull b) {
    ull r;
    asm("add.rn.f32x2 %0, %1, %2;" : "=l"(r) : "l"(a), "l"(b));
    return r;
}
__device__ __forceinline__ ull mul2(ull a, ull b) {
    ull r;
    asm("mul.rn.f32x2 %0, %1, %2;" : "=l"(r) : "l"(a), "l"(b));
    return r;
}
__device__ __forceinline__ ull fma2_(ull a, ull b, ull c) {
    ull r;
    asm("fma.rn.f32x2 %0, %1, %2, %3;" : "=l"(r) : "l"(a), "l"(b), "l"(c));
    return r;
}

// out[b,c] = sum_j u * (x_j - x_c) * W[j,c]
// t' = 0.505*(w2[0] + a w2[1] + a^2 w2[2] + a^3 w2[3]),  a = |x_c - x_j|
// u  = t' + (0.495/0.505)*|t'|          (== leaky_relu scaling, sign folded into d)
//
// grid = 256 blocks (4 rows = 2 packed row-pairs each), blockDim = (256 c, 2 j-halves).
// Each thread accumulates BOTH pairs over its 128-j half; halves combined via smem.
__global__ __launch_bounds__(512, 2) void son_main_kernel(
    const float* __restrict__ x, const float* __restrict__ w1,
    const float* __restrict__ w2, float* __restrict__ out)
{
    __shared__ float2 xs0[CC];        // (row r0,   row r0+1) * w1[j]
    __shared__ float2 xs1[CC];        // (row r0+2, row r0+3) * w1[j]
    __shared__ ull partial0[CC];
    __shared__ ull partial1[CC];

    const int c = threadIdx.x;
    const int h = threadIdx.y;
    const int r0 = blockIdx.x * 4;

    {
        float w1j = w1[c];
        if (h == 0) {
            float a0 = x[r0 * CC + c] * w1j;
            float a1 = x[(r0 + 1) * CC + c] * w1j;
            xs0[c] = make_float2(a0, a1);
        } else {
            float a2 = x[(r0 + 2) * CC + c] * w1j;
            float a3 = x[(r0 + 3) * CC + c] * w1j;
            xs1[c] = make_float2(a2, a3);
        }
    }
    __syncthreads();

    // prescaled polynomial coefficients (x 0.505)
    const float s0 = 0.505f * w2[0], s1 = 0.505f * w2[1];
    const float s2 = 0.505f * w2[2], s3 = 0.505f * w2[3];
    const ull C0 = pk2(s0, s0), C1 = pk2(s1, s1);
    const ull C2 = pk2(s2, s2), C3 = pk2(s3, s3);
    const float kf = 0.495f / 0.505f;
    const ull K = pk2(kf, kf);

    // -x_c for both pairs, via sign-bit flip (LOP3 with immediate, alu pipe)
    const ull nxc0 = (*reinterpret_cast<const ull*>(&xs0[c])) ^ 0x8000000080000000ULL;
    const ull nxc1 = (*reinterpret_cast<const ull*>(&xs1[c])) ^ 0x8000000080000000ULL;

    const ull* wp  = reinterpret_cast<const ull*>(g_W2) + h * 128 * CC + c;
    const ull* xp0 = reinterpret_cast<const ull*>(xs0) + h * 128;
    const ull* xp1 = reinterpret_cast<const ull*>(xs1) + h * 128;

    ull acc0 = 0ULL, acc1 = 0ULL;
#pragma unroll 4
    for (int j = 0; j < 128; j++) {
        ull w   = __ldg(wp + j * CC);   // (w, w), aligned pair, LDG.64, coalesced
        ull xj0 = xp0[j];               // LDS.64 broadcast
        ull xj1 = xp1[j];
        // pair 0
        ull d0 = add2(xj0, nxc0);
        ull a0 = d0 & 0x7fffffff7fffffffULL;
        ull t0 = fma2_(C3, a0, C2);
        t0 = fma2_(t0, a0, C1);
        t0 = fma2_(t0, a0, C0);
        ull u0 = fma2_(K, t0 & 0x7fffffff7fffffffULL, t0);
        acc0 = fma2_(u0, mul2(d0, w), acc0);
        // pair 1 (independent chain -> ILP 2)
        ull d1 = add2(xj1, nxc1);
        ull a1 = d1 & 0x7fffffff7fffffffULL;
        ull t1 = fma2_(C3, a1, C2);
        t1 = fma2_(t1, a1, C1);
        t1 = fma2_(t1, a1, C0);
        ull u1 = fma2_(K, t1 & 0x7fffffff7fffffffULL, t1);
        acc1 = fma2_(u1, mul2(d1, w), acc1);
    }

    if (h == 1) {
        partial0[c] = acc0;
        partial1[c] = acc1;
    }
    __syncthreads();
    if (h == 0) {
        acc0 = add2(acc0, partial0[c]);
        acc1 = add2(acc1, partial1[c]);
        float lo, hi;
        upk2(acc0, lo, hi);
        out[r0 * CC + c]       = lo;
        out[(r0 + 1) * CC + c] = hi;
        upk2(acc1, lo, hi);
        out[(r0 + 2) * CC + c] = lo;
        out[(r0 + 3) * CC + c] = hi;
    }
}

extern "C" void kernel_launch(void* const* d_in, const int* in_sizes, int n_in,
                              void* d_out, int out_size) {
    // Identify inputs by element count (robust to ordering):
    // x: 262144, w1: 256, w2: 4, w3: 32640, diff_indices: 8355840 (unused)
    const float* x = nullptr;
    const float* w1 = nullptr;
    const float* w2 = nullptr;
    const float* w3 = nullptr;
    for (int i = 0; i < n_in; i++) {
        switch (in_sizes[i]) {
            case BB * CC:            x  = (const float*)d_in[i]; break;
            case CC:                 w1 = (const float*)d_in[i]; break;
            case 4:                  w2 = (const float*)d_in[i]; break;
            case CC * (CC - 1) / 2:  w3 = (const float*)d_in[i]; break;
            default: break;  // diff_indices not needed
        }
    }

    build_W2_kernel<<<(CC * CC + 255) / 256, 256>>>(w3);
    son_main_kernel<<<BB / 4, dim3(CC, 2)>>>(x, w1, w2, (float*)d_out);
}